// round 8
// baseline (speedup 1.0000x reference)
#include <cuda_runtime.h>
#include <math.h>
#include <stdint.h>

#define TB 2048
#define CB 1024
#define BSZ 2
#define HH 16
#define DD 64
#define NCH 32   // chunks of 64 along T
#define BHN 32   // BSZ*HH

// ---------------- scratch (static device allocations; no cudaMalloc) ----------
__device__ float g_qkv[(size_t)BSZ * TB * 3 * CB];        // 50.3 MB (fp32)
__device__ float g_kv [(size_t)BHN * NCH * DD * DD];
__device__ float g_kz [(size_t)BHN * NCH * DD];
__device__ float g_y  [(size_t)BSZ * TB * CB];

__device__ __forceinline__ float phi(float x) { return x > 0.f ? x + 1.f : expf(x); }

__device__ __forceinline__ uint32_t f2tf32(float x) {
    uint32_t r;
    asm("cvt.rna.tf32.f32 %0, %1;" : "=r"(r) : "f"(x));
    return r;
}

#define MMA_TF32(C, A0, A1, A2, A3, B0, B1)                                     \
    asm volatile(                                                               \
        "mma.sync.aligned.m16n8k8.row.col.f32.tf32.tf32.f32 "                   \
        "{%0,%1,%2,%3}, {%4,%5,%6,%7}, {%8,%9}, {%0,%1,%2,%3};"                 \
        : "+f"((C)[0]), "+f"((C)[1]), "+f"((C)[2]), "+f"((C)[3])                \
        : "r"(A0), "r"(A1), "r"(A2), "r"(A3), "r"(B0), "r"(B1))

__device__ __forceinline__ uint32_t smem_u32(const void* p) {
    uint32_t a;
    asm("{ .reg .u64 t; cvta.to.shared.u64 t, %1; cvt.u32.u64 %0, t; }" : "=r"(a) : "l"(p));
    return a;
}

#define LDSM_X4(R0, R1, R2, R3, ADDR)                                           \
    asm volatile("ldmatrix.sync.aligned.m8n8.x4.shared.b16 {%0,%1,%2,%3}, [%4];"\
        : "=r"(R0), "=r"(R1), "=r"(R2), "=r"(R3) : "r"(ADDR))
#define LDSM_X2(R0, R1, ADDR)                                                   \
    asm volatile("ldmatrix.sync.aligned.m8n8.x2.shared.b16 {%0,%1}, [%2];"      \
        : "=r"(R0), "=r"(R1) : "r"(ADDR))

// ---------------- TF32 GEMM, ldmatrix fragment loads ---------------------------
// C(MxN)=A(MxK=1024)@B(KxN). 128x128 block, 8 warps (2x4), warp 64x32, K-step 32.
// As[128][36] k-major; Bsn[128][36] n-major (transposed in smem for ldmatrix).
__global__ __launch_bounds__(256) void tgemm_kernel(const float* __restrict__ A,
                                                    const float* __restrict__ B,
                                                    float* __restrict__ C, int N) {
    __shared__ uint32_t As [128 * 36];
    __shared__ uint32_t Bsn[128 * 36];
    const int K = 1024;

    int tid  = threadIdx.x;
    int lane = tid & 31;
    int warp = tid >> 5;
    int wm = (warp >> 2) * 64;         // 0 / 64
    int wn = (warp & 3) * 32;          // 0,32,64,96
    int bm = blockIdx.y * 128;
    int bn = blockIdx.x * 128;

    int ar = tid >> 3, ac = (tid & 7) << 2;   // A loader: 128 rows x 32 cols
    int brn = tid & 127;                      // B loader: n row 0..127
    int bkh = (tid >> 7) << 2;                // k sub-base 0 or 4
    const int lq = lane >> 2;
    const int lr = lane & 3;

    uint32_t aBase = smem_u32(As);
    uint32_t bBase = smem_u32(Bsn);
    // per-lane ldmatrix row-address offsets (bytes)
    uint32_t offA = ((((lane >> 3) & 1) * 8 + (lane & 7)) * 36 + (lane >> 4) * 4) * 4;
    uint32_t offB = ((lane & 7) * 36 + ((lane >> 3) & 1) * 4) * 4;

    float acc[4][4][4];
#pragma unroll
    for (int mi = 0; mi < 4; mi++)
#pragma unroll
        for (int ni = 0; ni < 4; ni++)
#pragma unroll
            for (int r = 0; r < 4; r++) acc[mi][ni][r] = 0.f;

    for (int k0 = 0; k0 < K; k0 += 32) {
        float4 a[4];
        float bb[4][4];
#pragma unroll
        for (int i = 0; i < 4; i++)
            a[i] = *(const float4*)(A + (size_t)(bm + ar + i * 32) * K + k0 + ac);
#pragma unroll
        for (int i = 0; i < 4; i++) {
            int kk = k0 + bkh + i * 8;
#pragma unroll
            for (int j = 0; j < 4; j++)
                bb[i][j] = B[(size_t)(kk + j) * N + bn + brn];
        }
        __syncthreads();
#pragma unroll
        for (int i = 0; i < 4; i++) {
            uint4 o;
            o.x = f2tf32(a[i].x); o.y = f2tf32(a[i].y);
            o.z = f2tf32(a[i].z); o.w = f2tf32(a[i].w);
            *(uint4*)&As[(ar + i * 32) * 36 + ac] = o;
        }
#pragma unroll
        for (int i = 0; i < 4; i++) {
            uint4 o;
            o.x = f2tf32(bb[i][0]); o.y = f2tf32(bb[i][1]);
            o.z = f2tf32(bb[i][2]); o.w = f2tf32(bb[i][3]);
            *(uint4*)&Bsn[brn * 36 + bkh + i * 8] = o;
        }
        __syncthreads();

#pragma unroll
        for (int ks = 0; ks < 4; ks++) {
            int kb = ks * 8;
            uint32_t af[4][4], bf[4][2];
#pragma unroll
            for (int mi = 0; mi < 4; mi++) {
                uint32_t ad = aBase + (((wm + mi * 16) * 36 + kb) << 2) + offA;
                LDSM_X4(af[mi][0], af[mi][1], af[mi][2], af[mi][3], ad);
            }
#pragma unroll
            for (int ni = 0; ni < 4; ni++) {
                uint32_t bd = bBase + (((wn + ni * 8) * 36 + kb) << 2) + offB;
                LDSM_X2(bf[ni][0], bf[ni][1], bd);
            }
#pragma unroll
            for (int mi = 0; mi < 4; mi++)
#pragma unroll
                for (int ni = 0; ni < 4; ni++)
                    MMA_TF32(acc[mi][ni], af[mi][0], af[mi][1], af[mi][2], af[mi][3],
                             bf[ni][0], bf[ni][1]);
        }
    }

#pragma unroll
    for (int mi = 0; mi < 4; mi++)
#pragma unroll
        for (int ni = 0; ni < 4; ni++) {
            int r = bm + wm + mi * 16 + lq;
            int c = bn + wn + ni * 8 + lr * 2;
            *(float2*)(C + (size_t)r * N + c) =
                make_float2(acc[mi][ni][0], acc[mi][ni][1]);
            *(float2*)(C + (size_t)(r + 8) * N + c) =
                make_float2(acc[mi][ni][2], acc[mi][ni][3]);
        }
}

// ---------------- Phase A: per-chunk KV = phi(K)^T V  and  kz = sum phi(k) ----
__global__ __launch_bounds__(256) void chunk_kv_kernel() {
    int bid = blockIdx.x;
    int bh = bid >> 5, c = bid & 31;
    int b = bh >> 4, h = bh & 15;
    int tid = threadIdx.x;
    __shared__ float sK[64][65];
    __shared__ float sV[64][65];

    const float* base = g_qkv + (size_t)(b * TB + c * 64) * (3 * CB) + h * 64;
#pragma unroll
    for (int it = 0; it < 4; it++) {
        int idx = tid + it * 256;
        int r = idx >> 4;
        int c4 = (idx & 15) << 2;
        float4 kk = *(const float4*)(base + (size_t)r * (3 * CB) + CB + c4);
        float4 vv = *(const float4*)(base + (size_t)r * (3 * CB) + 2 * CB + c4);
        sK[r][c4 + 0] = phi(kk.x); sK[r][c4 + 1] = phi(kk.y);
        sK[r][c4 + 2] = phi(kk.z); sK[r][c4 + 3] = phi(kk.w);
        sV[r][c4 + 0] = vv.x; sV[r][c4 + 1] = vv.y;
        sV[r][c4 + 2] = vv.z; sV[r][c4 + 3] = vv.w;
    }
    __syncthreads();

    int ii0 = (tid >> 4) << 2;
    int jj0 = (tid & 15) << 2;
    float a[4][4];
#pragma unroll
    for (int i = 0; i < 4; i++)
#pragma unroll
        for (int j = 0; j < 4; j++) a[i][j] = 0.f;

#pragma unroll 4
    for (int t = 0; t < 64; t++) {
        float kr[4], vr[4];
#pragma unroll
        for (int i = 0; i < 4; i++) kr[i] = sK[t][ii0 + i];
#pragma unroll
        for (int j = 0; j < 4; j++) vr[j] = sV[t][jj0 + j];
#pragma unroll
        for (int i = 0; i < 4; i++)
#pragma unroll
            for (int j = 0; j < 4; j++)
                a[i][j] += kr[i] * vr[j];
    }

    float* kvout = g_kv + (size_t)(bh * NCH + c) * (DD * DD);
#pragma unroll
    for (int i = 0; i < 4; i++)
        *(float4*)&kvout[(ii0 + i) * 64 + jj0] =
            make_float4(a[i][0], a[i][1], a[i][2], a[i][3]);

    if (tid < 64) {
        float s = 0.f;
#pragma unroll 8
        for (int t = 0; t < 64; t++) s += sK[t][tid];
        g_kz[(size_t)(bh * NCH + c) * 64 + tid] = s;
    }
}

// ---------------- Phase B: exclusive prefix over chunks ------------------------
__global__ void scan_all_kernel() {
    int e = blockIdx.x * 256 + threadIdx.x;
    if (e < BHN * 4096) {
        int bh = e >> 12, ij = e & 4095;
        float* p = g_kv + (size_t)bh * NCH * 4096 + ij;
        float run = 0.f;
#pragma unroll 4
        for (int c = 0; c < NCH; c++) {
            float v = p[(size_t)c * 4096];
            p[(size_t)c * 4096] = run;
            run += v;
        }
    } else if (e < BHN * 4096 + BHN * 64) {
        int e2 = e - BHN * 4096;
        int bh = e2 >> 6, i = e2 & 63;
        float* p = g_kz + (size_t)bh * NCH * 64 + i;
        float run = 0.f;
#pragma unroll 4
        for (int c = 0; c < NCH; c++) {
            float v = p[(size_t)c * 64];
            p[(size_t)c * 64] = run;
            run += v;
        }
    }
}

// ---------------- Phase C: tensor-core per-chunk output (R6 version) ----------
#define ATTN_SMEM_WORDS (64*68 + 64*72*3 + 64)
#define ATTN_SMEM_BYTES (ATTN_SMEM_WORDS * 4)

__global__ __launch_bounds__(128) void attn_out_tc_kernel() {
    extern __shared__ uint32_t sm[];
    uint32_t* sQ  = sm;                          // [64][68]
    uint32_t* sKt = sm + 64 * 68;                // [64][72] (phase 1 only)
    uint32_t* sP  = sKt;                         // alias (phase 2)
    uint32_t* sS  = sm + 64 * 68 + 64 * 72;      // [64][72]
    uint32_t* sV  = sS + 64 * 72;                // [64][72]
    float* sDen = (float*)(sV + 64 * 72);        // [64]

    int bid = blockIdx.x;
    int bh = bid >> 5, cidx = bid & 31;
    int b = bh >> 4, h = bh & 15;
    int tid = threadIdx.x;
    int lane = tid & 31;
    int warp = tid >> 5;
    int wrow = warp * 16;
    int lq = lane >> 2, lr = lane & 3;

    const float* base = g_qkv + (size_t)(b * TB + cidx * 64) * (3 * CB) + h * 64;
    const float* Sg = g_kv + (size_t)(bh * NCH + cidx) * 4096;

#pragma unroll
    for (int it = 0; it < 8; it++) {
        int idx = it * 128 + tid;
        int r = idx >> 4, c4 = (idx & 15) << 2;
        float4 q4 = *(const float4*)(base + (size_t)r * (3 * CB) + c4);
        float4 v4 = *(const float4*)(base + (size_t)r * (3 * CB) + 2 * CB + c4);
        float4 s4 = *(const float4*)(Sg + r * 64 + c4);
        sQ[r * 68 + c4 + 0] = f2tf32(phi(q4.x));
        sQ[r * 68 + c4 + 1] = f2tf32(phi(q4.y));
        sQ[r * 68 + c4 + 2] = f2tf32(phi(q4.z));
        sQ[r * 68 + c4 + 3] = f2tf32(phi(q4.w));
        sV[r * 72 + c4 + 0] = f2tf32(v4.x);
        sV[r * 72 + c4 + 1] = f2tf32(v4.y);
        sV[r * 72 + c4 + 2] = f2tf32(v4.z);
        sV[r * 72 + c4 + 3] = f2tf32(v4.w);
        sS[r * 72 + c4 + 0] = f2tf32(s4.x);
        sS[r * 72 + c4 + 1] = f2tf32(s4.y);
        sS[r * 72 + c4 + 2] = f2tf32(s4.z);
        sS[r * 72 + c4 + 3] = f2tf32(s4.w);
        int tt = idx & 63, kc = (idx >> 6) << 2;
        float4 k4 = *(const float4*)(base + (size_t)tt * (3 * CB) + CB + kc);
        sKt[(kc + 0) * 72 + tt] = f2tf32(phi(k4.x));
        sKt[(kc + 1) * 72 + tt] = f2tf32(phi(k4.y));
        sKt[(kc + 2) * 72 + tt] = f2tf32(phi(k4.z));
        sKt[(kc + 3) * 72 + tt] = f2tf32(phi(k4.w));
    }
    if (tid < 64) {
        sV[tid * 72 + 64] = 0x3f800000u;
        sS[tid * 72 + 64] = f2tf32(g_kz[(size_t)(bh * NCH + cidx) * 64 + tid]);
#pragma unroll
        for (int j = 65; j < 72; j++) { sV[tid * 72 + j] = 0u; sS[tid * 72 + j] = 0u; }
    }
    __syncthreads();

    int r0 = wrow + lq, r1 = r0 + 8;

    float pc[8][4];
#pragma unroll
    for (int nt = 0; nt < 8; nt++)
#pragma unroll
        for (int r = 0; r < 4; r++) pc[nt][r] = 0.f;

#pragma unroll
    for (int ks = 0; ks < 8; ks++) {
        int kb = ks * 8;
        uint32_t a0 = sQ[r0 * 68 + kb + lr];
        uint32_t a1 = sQ[r1 * 68 + kb + lr];
        uint32_t a2 = sQ[r0 * 68 + kb + 4 + lr];
        uint32_t a3 = sQ[r1 * 68 + kb + 4 + lr];
#pragma unroll
        for (int nt = 0; nt < 8; nt++) {
            uint32_t b0 = sKt[(kb + lr) * 72 + nt * 8 + lq];
            uint32_t b1 = sKt[(kb + 4 + lr) * 72 + nt * 8 + lq];
            MMA_TF32(pc[nt], a0, a1, a2, a3, b0, b1);
        }
    }
    __syncthreads();

#pragma unroll
    for (int nt = 0; nt < 8; nt++) {
        int s0 = nt * 8 + 2 * lr;
        sP[r0 * 68 + s0    ] = f2tf32((s0     <= r0) ? pc[nt][0] : 0.f);
        sP[r0 * 68 + s0 + 1] = f2tf32((s0 + 1 <= r0) ? pc[nt][1] : 0.f);
        sP[r1 * 68 + s0    ] = f2tf32((s0     <= r1) ? pc[nt][2] : 0.f);
        sP[r1 * 68 + s0 + 1] = f2tf32((s0 + 1 <= r1) ? pc[nt][3] : 0.f);
    }
    __syncwarp();

    float acc[9][4];
#pragma unroll
    for (int nt = 0; nt < 9; nt++)
#pragma unroll
        for (int r = 0; r < 4; r++) acc[nt][r] = 0.f;

#pragma unroll
    for (int ks = 0; ks < 8; ks++) {
        int kb = ks * 8;
        uint32_t q0 = sQ[r0 * 68 + kb + lr];
        uint32_t q1 = sQ[r1 * 68 + kb + lr];
        uint32_t q2 = sQ[r0 * 68 + kb + 4 + lr];
        uint32_t q3 = sQ[r1 * 68 + kb + 4 + lr];
        uint32_t p0 = sP[r0 * 68 + kb + lr];
        uint32_t p1 = sP[r1 * 68 + kb + lr];
        uint32_t p2 = sP[r0 * 68 + kb + 4 + lr];
        uint32_t p3 = sP[r1 * 68 + kb + 4 + lr];
#pragma unroll
        for (int nt = 0; nt < 9; nt++) {
            int n0 = nt * 8;
            uint32_t bs0 = sS[(kb + lr) * 72 + n0 + lq];
            uint32_t bs1 = sS[(kb + 4 + lr) * 72 + n0 + lq];
            MMA_TF32(acc[nt], q0, q1, q2, q3, bs0, bs1);
            uint32_t bv0 = sV[(kb + lr) * 72 + n0 + lq];
            uint32_t bv1 = sV[(kb + 4 + lr) * 72 + n0 + lq];
            MMA_TF32(acc[nt], p0, p1, p2, p3, bv0, bv1);
        }
    }

    if (lr == 0) { sDen[r0] = acc[8][0]; sDen[r1] = acc[8][2]; }
    __syncwarp();
    float inv0 = 1.f / (sDen[r0] + 1e-6f);
    float inv1 = 1.f / (sDen[r1] + 1e-6f);

    float* yb = g_y + (size_t)(b * TB + cidx * 64) * CB + h * 64;
#pragma unroll
    for (int nt = 0; nt < 8; nt++) {
        int col = nt * 8 + 2 * lr;
        uint2 o0, o1;
        o0.x = f2tf32(acc[nt][0] * inv0); o0.y = f2tf32(acc[nt][1] * inv0);
        o1.x = f2tf32(acc[nt][2] * inv1); o1.y = f2tf32(acc[nt][3] * inv1);
        *(uint2*)(yb + (size_t)r0 * CB + col) = o0;
        *(uint2*)(yb + (size_t)r1 * CB + col) = o1;
    }
}

// ---------------- launch ------------------------------------------------------
extern "C" void kernel_launch(void* const* d_in, const int* in_sizes, int n_in,
                              void* d_out, int out_size) {
    const float* x      = (const float*)d_in[0];
    const float* w_attn = (const float*)d_in[1];
    const float* w_proj = (const float*)d_in[2];
    float* out = (float*)d_out;

    cudaFuncSetAttribute(attn_out_tc_kernel,
                         cudaFuncAttributeMaxDynamicSharedMemorySize, ATTN_SMEM_BYTES);

    float *qkv, *y;
    cudaGetSymbolAddress((void**)&qkv, g_qkv);
    cudaGetSymbolAddress((void**)&y,   g_y);

    dim3 g1(3 * CB / 128, BSZ * TB / 128);   // (24, 32)
    tgemm_kernel<<<g1, 256>>>(x, w_attn, qkv, 3 * CB);

    chunk_kv_kernel<<<BHN * NCH, 256>>>();
    scan_all_kernel<<<(BHN * 4096 + BHN * 64 + 255) / 256, 256>>>();
    attn_out_tc_kernel<<<BHN * NCH, 128, ATTN_SMEM_BYTES>>>();

    dim3 g2(CB / 128, BSZ * TB / 128);       // (8, 32)
    tgemm_kernel<<<g2, 256>>>(y, w_proj, out, CB);
}

// round 9
// speedup vs baseline: 1.1391x; 1.1391x over previous
#include <cuda_runtime.h>
#include <math.h>
#include <stdint.h>

#define TB 2048
#define CB 1024
#define BSZ 2
#define HH 16
#define DD 64
#define NCH 32   // chunks of 64 along T
#define BHN 32   // BSZ*HH

// ---------------- scratch (static device allocations; no cudaMalloc) ----------
__device__ float g_qkv[(size_t)BSZ * TB * 3 * CB];        // 50.3 MB (fp32)
__device__ float g_kv [(size_t)BHN * NCH * DD * DD];
__device__ float g_kz [(size_t)BHN * NCH * DD];
__device__ float g_y  [(size_t)BSZ * TB * CB];

__device__ __forceinline__ float phi(float x) { return x > 0.f ? x + 1.f : expf(x); }

__device__ __forceinline__ uint32_t f2tf32(float x) {
    uint32_t r;
    asm("cvt.rna.tf32.f32 %0, %1;" : "=r"(r) : "f"(x));
    return r;
}

#define MMA_TF32(C, A0, A1, A2, A3, B0, B1)                                     \
    asm volatile(                                                               \
        "mma.sync.aligned.m16n8k8.row.col.f32.tf32.tf32.f32 "                   \
        "{%0,%1,%2,%3}, {%4,%5,%6,%7}, {%8,%9}, {%0,%1,%2,%3};"                 \
        : "+f"((C)[0]), "+f"((C)[1]), "+f"((C)[2]), "+f"((C)[3])                \
        : "r"(A0), "r"(A1), "r"(A2), "r"(A3), "r"(B0), "r"(B1))

// ---------------- TF32 GEMM: software-pipelined loads ahead of MMA -------------
// C(MxN)=A(MxK=1024)@B(KxN). 128x128 block, 8 warps (2x4), warp 64x32, K-step 32.
// Loop order: sync; STS(t); sync; LDG(t+1); MMA(t)  -> LDG latency hides under MMA.
__device__ __forceinline__ void tgemm_body(const float* __restrict__ A,
                                           const float* __restrict__ B,
                                           float* __restrict__ C,
                                           int N) {
    __shared__ uint32_t As[128][36];   // bank = (4*row+col)%32 -> conflict free
    __shared__ uint32_t Bs[32][136];   // bank = (8*k+n)%32   -> conflict free
    const int K = 1024;
    const int NT = K / 32;             // 32 tiles

    int tid  = threadIdx.x;
    int lane = tid & 31;
    int warp = tid >> 5;
    int wm = (warp >> 2) * 64;         // 0 / 64
    int wn = (warp & 3) * 32;          // 0,32,64,96
    int bm = blockIdx.y * 128;
    int bn = blockIdx.x * 128;

    float acc[4][4][4];
#pragma unroll
    for (int mi = 0; mi < 4; mi++)
#pragma unroll
        for (int ni = 0; ni < 4; ni++)
#pragma unroll
            for (int r = 0; r < 4; r++) acc[mi][ni][r] = 0.f;

    int ar = tid >> 3, ac = (tid & 7) << 2;   // A loader: 128 rows x 32 cols
    int br = tid >> 5, bc = (tid & 31) << 2;  // B loader: 32 rows x 128 cols
    const int lq = lane >> 2;
    const int lr = lane & 3;

    const float* Ab = A + (size_t)(bm + ar) * K + ac;
    const float* Bb = B + (size_t)br * N + bn + bc;

    float4 a[4], b[4];
#pragma unroll
    for (int i = 0; i < 4; i++) a[i] = *(const float4*)(Ab + (size_t)(i * 32) * K);
#pragma unroll
    for (int i = 0; i < 4; i++) b[i] = *(const float4*)(Bb + (size_t)(i * 8) * N);

    for (int t = 0; t < NT; t++) {
        __syncthreads();
#pragma unroll
        for (int i = 0; i < 4; i++) {
            int rr = ar + i * 32;
            As[rr][ac + 0] = f2tf32(a[i].x); As[rr][ac + 1] = f2tf32(a[i].y);
            As[rr][ac + 2] = f2tf32(a[i].z); As[rr][ac + 3] = f2tf32(a[i].w);
        }
#pragma unroll
        for (int i = 0; i < 4; i++) {
            int rr = br + i * 8;
            Bs[rr][bc + 0] = f2tf32(b[i].x); Bs[rr][bc + 1] = f2tf32(b[i].y);
            Bs[rr][bc + 2] = f2tf32(b[i].z); Bs[rr][bc + 3] = f2tf32(b[i].w);
        }
        __syncthreads();

        if (t + 1 < NT) {                     // prefetch next tile; hides under MMA
            int k0 = (t + 1) * 32;
#pragma unroll
            for (int i = 0; i < 4; i++)
                a[i] = *(const float4*)(Ab + (size_t)(i * 32) * K + k0);
#pragma unroll
            for (int i = 0; i < 4; i++)
                b[i] = *(const float4*)(Bb + (size_t)(k0 + i * 8) * N);
        }

#pragma unroll
        for (int ks = 0; ks < 4; ks++) {
            int kb = ks * 8;
            uint32_t af[4][4], bf[4][2];
#pragma unroll
            for (int mi = 0; mi < 4; mi++) {
                int r0 = wm + mi * 16 + lq;
                af[mi][0] = As[r0    ][kb + lr];
                af[mi][1] = As[r0 + 8][kb + lr];
                af[mi][2] = As[r0    ][kb + 4 + lr];
                af[mi][3] = As[r0 + 8][kb + 4 + lr];
            }
#pragma unroll
            for (int ni = 0; ni < 4; ni++) {
                int c0 = wn + ni * 8 + lq;
                bf[ni][0] = Bs[kb + lr    ][c0];
                bf[ni][1] = Bs[kb + 4 + lr][c0];
            }
#pragma unroll
            for (int mi = 0; mi < 4; mi++)
#pragma unroll
                for (int ni = 0; ni < 4; ni++)
                    MMA_TF32(acc[mi][ni], af[mi][0], af[mi][1], af[mi][2], af[mi][3],
                             bf[ni][0], bf[ni][1]);
        }
    }

#pragma unroll
    for (int mi = 0; mi < 4; mi++)
#pragma unroll
        for (int ni = 0; ni < 4; ni++) {
            int r = bm + wm + mi * 16 + lq;
            int c = bn + wn + ni * 8 + lr * 2;
            *(float2*)(C + (size_t)r * N + c) =
                make_float2(acc[mi][ni][0], acc[mi][ni][1]);
            *(float2*)(C + (size_t)(r + 8) * N + c) =
                make_float2(acc[mi][ni][2], acc[mi][ni][3]);
        }
}

__global__ __launch_bounds__(256) void gemm_qkv_kernel(const float* __restrict__ x,
                                                       const float* __restrict__ w) {
    tgemm_body(x, w, g_qkv, 3 * CB);
}
__global__ __launch_bounds__(256) void gemm_proj_kernel(const float* __restrict__ w,
                                                        float* __restrict__ out) {
    tgemm_body(g_y, w, out, CB);
}

// ---------------- Phase A: per-chunk KV = phi(K)^T V  and  kz = sum phi(k) ----
__global__ __launch_bounds__(256) void chunk_kv_kernel() {
    int bid = blockIdx.x;
    int bh = bid >> 5, c = bid & 31;
    int b = bh >> 4, h = bh & 15;
    int tid = threadIdx.x;
    __shared__ float sK[64][65];
    __shared__ float sV[64][65];

    const float* base = g_qkv + (size_t)(b * TB + c * 64) * (3 * CB) + h * 64;
#pragma unroll
    for (int it = 0; it < 4; it++) {
        int idx = tid + it * 256;
        int r = idx >> 4;
        int c4 = (idx & 15) << 2;
        float4 kk = *(const float4*)(base + (size_t)r * (3 * CB) + CB + c4);
        float4 vv = *(const float4*)(base + (size_t)r * (3 * CB) + 2 * CB + c4);
        sK[r][c4 + 0] = phi(kk.x); sK[r][c4 + 1] = phi(kk.y);
        sK[r][c4 + 2] = phi(kk.z); sK[r][c4 + 3] = phi(kk.w);
        sV[r][c4 + 0] = vv.x; sV[r][c4 + 1] = vv.y;
        sV[r][c4 + 2] = vv.z; sV[r][c4 + 3] = vv.w;
    }
    __syncthreads();

    int ii0 = (tid >> 4) << 2;
    int jj0 = (tid & 15) << 2;
    float a[4][4];
#pragma unroll
    for (int i = 0; i < 4; i++)
#pragma unroll
        for (int j = 0; j < 4; j++) a[i][j] = 0.f;

#pragma unroll 4
    for (int t = 0; t < 64; t++) {
        float kr[4], vr[4];
#pragma unroll
        for (int i = 0; i < 4; i++) kr[i] = sK[t][ii0 + i];
#pragma unroll
        for (int j = 0; j < 4; j++) vr[j] = sV[t][jj0 + j];
#pragma unroll
        for (int i = 0; i < 4; i++)
#pragma unroll
            for (int j = 0; j < 4; j++)
                a[i][j] += kr[i] * vr[j];
    }

    float* kvout = g_kv + (size_t)(bh * NCH + c) * (DD * DD);
#pragma unroll
    for (int i = 0; i < 4; i++)
        *(float4*)&kvout[(ii0 + i) * 64 + jj0] =
            make_float4(a[i][0], a[i][1], a[i][2], a[i][3]);

    if (tid < 64) {
        float s = 0.f;
#pragma unroll 8
        for (int t = 0; t < 64; t++) s += sK[t][tid];
        g_kz[(size_t)(bh * NCH + c) * 64 + tid] = s;
    }
}

// ---------------- Phase B: exclusive prefix over chunks ------------------------
__global__ void scan_all_kernel() {
    int e = blockIdx.x * 256 + threadIdx.x;
    if (e < BHN * 4096) {
        int bh = e >> 12, ij = e & 4095;
        float* p = g_kv + (size_t)bh * NCH * 4096 + ij;
        float run = 0.f;
#pragma unroll 4
        for (int c = 0; c < NCH; c++) {
            float v = p[(size_t)c * 4096];
            p[(size_t)c * 4096] = run;
            run += v;
        }
    } else if (e < BHN * 4096 + BHN * 64) {
        int e2 = e - BHN * 4096;
        int bh = e2 >> 6, i = e2 & 63;
        float* p = g_kz + (size_t)bh * NCH * 64 + i;
        float run = 0.f;
#pragma unroll 4
        for (int c = 0; c < NCH; c++) {
            float v = p[(size_t)c * 64];
            p[(size_t)c * 64] = run;
            run += v;
        }
    }
}

// ---------------- Phase C: tensor-core per-chunk output ------------------------
#define ATTN_SMEM_WORDS (64*68 + 64*72*3 + 64)
#define ATTN_SMEM_BYTES (ATTN_SMEM_WORDS * 4)

__global__ __launch_bounds__(128) void attn_out_tc_kernel() {
    extern __shared__ uint32_t sm[];
    uint32_t* sQ  = sm;                          // [64][68]
    uint32_t* sKt = sm + 64 * 68;                // [64][72] (phase 1 only)
    uint32_t* sP  = sKt;                         // alias (phase 2)
    uint32_t* sS  = sm + 64 * 68 + 64 * 72;      // [64][72]
    uint32_t* sV  = sS + 64 * 72;                // [64][72]
    float* sDen = (float*)(sV + 64 * 72);        // [64]

    int bid = blockIdx.x;
    int bh = bid >> 5, cidx = bid & 31;
    int b = bh >> 4, h = bh & 15;
    int tid = threadIdx.x;
    int lane = tid & 31;
    int warp = tid >> 5;
    int wrow = warp * 16;
    int lq = lane >> 2, lr = lane & 3;

    const float* base = g_qkv + (size_t)(b * TB + cidx * 64) * (3 * CB) + h * 64;
    const float* Sg = g_kv + (size_t)(bh * NCH + cidx) * 4096;

#pragma unroll
    for (int it = 0; it < 8; it++) {
        int idx = it * 128 + tid;
        int r = idx >> 4, c4 = (idx & 15) << 2;
        float4 q4 = *(const float4*)(base + (size_t)r * (3 * CB) + c4);
        float4 v4 = *(const float4*)(base + (size_t)r * (3 * CB) + 2 * CB + c4);
        float4 s4 = *(const float4*)(Sg + r * 64 + c4);
        sQ[r * 68 + c4 + 0] = f2tf32(phi(q4.x));
        sQ[r * 68 + c4 + 1] = f2tf32(phi(q4.y));
        sQ[r * 68 + c4 + 2] = f2tf32(phi(q4.z));
        sQ[r * 68 + c4 + 3] = f2tf32(phi(q4.w));
        sV[r * 72 + c4 + 0] = f2tf32(v4.x);
        sV[r * 72 + c4 + 1] = f2tf32(v4.y);
        sV[r * 72 + c4 + 2] = f2tf32(v4.z);
        sV[r * 72 + c4 + 3] = f2tf32(v4.w);
        sS[r * 72 + c4 + 0] = f2tf32(s4.x);
        sS[r * 72 + c4 + 1] = f2tf32(s4.y);
        sS[r * 72 + c4 + 2] = f2tf32(s4.z);
        sS[r * 72 + c4 + 3] = f2tf32(s4.w);
        int tt = idx & 63, kc = (idx >> 6) << 2;
        float4 k4 = *(const float4*)(base + (size_t)tt * (3 * CB) + CB + kc);
        sKt[(kc + 0) * 72 + tt] = f2tf32(phi(k4.x));
        sKt[(kc + 1) * 72 + tt] = f2tf32(phi(k4.y));
        sKt[(kc + 2) * 72 + tt] = f2tf32(phi(k4.z));
        sKt[(kc + 3) * 72 + tt] = f2tf32(phi(k4.w));
    }
    if (tid < 64) {
        sV[tid * 72 + 64] = 0x3f800000u;
        sS[tid * 72 + 64] = f2tf32(g_kz[(size_t)(bh * NCH + cidx) * 64 + tid]);
#pragma unroll
        for (int j = 65; j < 72; j++) { sV[tid * 72 + j] = 0u; sS[tid * 72 + j] = 0u; }
    }
    __syncthreads();

    int r0 = wrow + lq, r1 = r0 + 8;

    float pc[8][4];
#pragma unroll
    for (int nt = 0; nt < 8; nt++)
#pragma unroll
        for (int r = 0; r < 4; r++) pc[nt][r] = 0.f;

#pragma unroll
    for (int ks = 0; ks < 8; ks++) {
        int kb = ks * 8;
        uint32_t a0 = sQ[r0 * 68 + kb + lr];
        uint32_t a1 = sQ[r1 * 68 + kb + lr];
        uint32_t a2 = sQ[r0 * 68 + kb + 4 + lr];
        uint32_t a3 = sQ[r1 * 68 + kb + 4 + lr];
#pragma unroll
        for (int nt = 0; nt < 8; nt++) {
            uint32_t b0 = sKt[(kb + lr) * 72 + nt * 8 + lq];
            uint32_t b1 = sKt[(kb + 4 + lr) * 72 + nt * 8 + lq];
            MMA_TF32(pc[nt], a0, a1, a2, a3, b0, b1);
        }
    }
    __syncthreads();

#pragma unroll
    for (int nt = 0; nt < 8; nt++) {
        int s0 = nt * 8 + 2 * lr;
        sP[r0 * 68 + s0    ] = f2tf32((s0     <= r0) ? pc[nt][0] : 0.f);
        sP[r0 * 68 + s0 + 1] = f2tf32((s0 + 1 <= r0) ? pc[nt][1] : 0.f);
        sP[r1 * 68 + s0    ] = f2tf32((s0     <= r1) ? pc[nt][2] : 0.f);
        sP[r1 * 68 + s0 + 1] = f2tf32((s0 + 1 <= r1) ? pc[nt][3] : 0.f);
    }
    __syncwarp();

    float acc[9][4];
#pragma unroll
    for (int nt = 0; nt < 9; nt++)
#pragma unroll
        for (int r = 0; r < 4; r++) acc[nt][r] = 0.f;

#pragma unroll
    for (int ks = 0; ks < 8; ks++) {
        int kb = ks * 8;
        uint32_t q0 = sQ[r0 * 68 + kb + lr];
        uint32_t q1 = sQ[r1 * 68 + kb + lr];
        uint32_t q2 = sQ[r0 * 68 + kb + 4 + lr];
        uint32_t q3 = sQ[r1 * 68 + kb + 4 + lr];
        uint32_t p0 = sP[r0 * 68 + kb + lr];
        uint32_t p1 = sP[r1 * 68 + kb + lr];
        uint32_t p2 = sP[r0 * 68 + kb + 4 + lr];
        uint32_t p3 = sP[r1 * 68 + kb + 4 + lr];
#pragma unroll
        for (int nt = 0; nt < 9; nt++) {
            int n0 = nt * 8;
            uint32_t bs0 = sS[(kb + lr) * 72 + n0 + lq];
            uint32_t bs1 = sS[(kb + 4 + lr) * 72 + n0 + lq];
            MMA_TF32(acc[nt], q0, q1, q2, q3, bs0, bs1);
            uint32_t bv0 = sV[(kb + lr) * 72 + n0 + lq];
            uint32_t bv1 = sV[(kb + 4 + lr) * 72 + n0 + lq];
            MMA_TF32(acc[nt], p0, p1, p2, p3, bv0, bv1);
        }
    }

    if (lr == 0) { sDen[r0] = acc[8][0]; sDen[r1] = acc[8][2]; }
    __syncwarp();
    float inv0 = 1.f / (sDen[r0] + 1e-6f);
    float inv1 = 1.f / (sDen[r1] + 1e-6f);

    float* yb = g_y + (size_t)(b * TB + cidx * 64) * CB + h * 64;
#pragma unroll
    for (int nt = 0; nt < 8; nt++) {
        int col = nt * 8 + 2 * lr;
        uint2 o0, o1;
        o0.x = f2tf32(acc[nt][0] * inv0); o0.y = f2tf32(acc[nt][1] * inv0);
        o1.x = f2tf32(acc[nt][2] * inv1); o1.y = f2tf32(acc[nt][3] * inv1);
        *(uint2*)(yb + (size_t)r0 * CB + col) = o0;
        *(uint2*)(yb + (size_t)r1 * CB + col) = o1;
    }
}

// ---------------- launch ------------------------------------------------------
extern "C" void kernel_launch(void* const* d_in, const int* in_sizes, int n_in,
                              void* d_out, int out_size) {
    const float* x      = (const float*)d_in[0];
    const float* w_attn = (const float*)d_in[1];
    const float* w_proj = (const float*)d_in[2];
    float* out = (float*)d_out;

    cudaFuncSetAttribute(attn_out_tc_kernel,
                         cudaFuncAttributeMaxDynamicSharedMemorySize, ATTN_SMEM_BYTES);

    dim3 g1(3 * CB / 128, BSZ * TB / 128);   // (24, 32)
    gemm_qkv_kernel<<<g1, 256>>>(x, w_attn);

    chunk_kv_kernel<<<BHN * NCH, 256>>>();
    scan_all_kernel<<<(BHN * 4096 + BHN * 64 + 255) / 256, 256>>>();
    attn_out_tc_kernel<<<BHN * NCH, 128, ATTN_SMEM_BYTES>>>();

    dim3 g2(CB / 128, BSZ * TB / 128);       // (8, 32)
    gemm_proj_kernel<<<g2, 256>>>(w_proj, out);
}

// round 11
// speedup vs baseline: 1.4757x; 1.2955x over previous
#include <cuda_runtime.h>
#include <math.h>
#include <stdint.h>

#define TB 2048
#define CB 1024
#define BSZ 2
#define HH 16
#define DD 64
#define NCH 32   // chunks of 64 along T
#define BHN 32   // BSZ*HH

// ---------------- scratch (static device allocations; no cudaMalloc) ----------
__device__ float    g_qkv[(size_t)BSZ * TB * 3 * CB];      // 50.3 MB fp32
__device__ float    g_kv [(size_t)BHN * NCH * DD * DD];
__device__ float    g_kz [(size_t)BHN * NCH * DD];
__device__ uint32_t g_xh [(size_t)BSZ * TB * CB / 2];      // x packed fp16x2 along K
__device__ uint32_t g_yh [(size_t)BSZ * TB * CB / 2];      // y packed fp16x2 along K
__device__ uint32_t g_wah[(size_t)CB / 2 * 3 * CB];        // w_attn [K/2][3072] k-pair words
__device__ uint32_t g_wph[(size_t)CB / 2 * CB];            // w_proj [K/2][1024]

__device__ __forceinline__ float phi(float x) { return x > 0.f ? x + 1.f : expf(x); }

__device__ __forceinline__ uint32_t f2tf32(float x) {
    uint32_t r;
    asm("cvt.rna.tf32.f32 %0, %1;" : "=r"(r) : "f"(x));
    return r;
}
__device__ __forceinline__ uint32_t pack_h2(float lo, float hi) {
    uint32_t r;                              // low 16 bits = lo (lower k index)
    asm("cvt.rn.f16x2.f32 %0, %1, %2;" : "=r"(r) : "f"(hi), "f"(lo));
    return r;
}

#define MMA_TF32(C, A0, A1, A2, A3, B0, B1)                                     \
    asm volatile(                                                               \
        "mma.sync.aligned.m16n8k8.row.col.f32.tf32.tf32.f32 "                   \
        "{%0,%1,%2,%3}, {%4,%5,%6,%7}, {%8,%9}, {%0,%1,%2,%3};"                 \
        : "+f"((C)[0]), "+f"((C)[1]), "+f"((C)[2]), "+f"((C)[3])                \
        : "r"(A0), "r"(A1), "r"(A2), "r"(A3), "r"(B0), "r"(B1))

#define MMA_F16(C, A0, A1, A2, A3, B0, B1)                                      \
    asm volatile(                                                               \
        "mma.sync.aligned.m16n8k16.row.col.f32.f16.f16.f32 "                    \
        "{%0,%1,%2,%3}, {%4,%5,%6,%7}, {%8,%9}, {%0,%1,%2,%3};"                 \
        : "+f"((C)[0]), "+f"((C)[1]), "+f"((C)[2]), "+f"((C)[3])                \
        : "r"(A0), "r"(A1), "r"(A2), "r"(A3), "r"(B0), "r"(B1))

// ---------------- pack pre-passes ---------------------------------------------
// pairs along contiguous dim (for A operands: x)
__global__ __launch_bounds__(256) void packA_kernel(const float2* __restrict__ src,
                                                    uint32_t* __restrict__ dst, int n) {
    int i = blockIdx.x * 256 + threadIdx.x;
    if (i < n) {
        float2 v = src[i];
        dst[i] = pack_h2(v.x, v.y);
    }
}
// B [K][N] fp32 -> [K/2][N] words, word(kp,n) = (f16 B[2kp][n], f16 B[2kp+1][n])
__global__ __launch_bounds__(256) void packB_kernel(const float* __restrict__ src,
                                                    uint32_t* __restrict__ dst,
                                                    int N, int total) {
    int i = blockIdx.x * 256 + threadIdx.x;
    if (i < total) {
        int kp = i / N, n = i - kp * N;
        float lo = src[(size_t)(2 * kp) * N + n];
        float hi = src[(size_t)(2 * kp + 1) * N + n];
        dst[i] = pack_h2(lo, hi);
    }
}

// ---------------- FP16 tensor GEMM: C(MxN)=A(Mx1024)@B(1024xN), fp32 accum ----
// 128x128 block, 8 warps (2x4), warp 64x32, k-tile 32 (=16 word-pairs, 2 k16 MMAs).
// As[128][20] words (pad: bank(20*lq+lr) distinct); Bs[16][136] (bank 8lr+lq).
__global__ __launch_bounds__(256) void hgemm_kernel(const uint32_t* __restrict__ Ah,
                                                    const uint32_t* __restrict__ Bh,
                                                    float* __restrict__ C, int N) {
    __shared__ uint32_t As[128 * 20];
    __shared__ uint32_t Bs[16 * 136];
    const int KW = 512;                 // words per A row
    const int NT = 32;                  // k tiles

    int tid  = threadIdx.x;
    int lane = tid & 31;
    int warp = tid >> 5;
    int wm = (warp >> 2) * 64;
    int wn = (warp & 3) * 32;
    int bm = blockIdx.y * 128;
    int bn = blockIdx.x * 128;
    const int lq = lane >> 2;
    const int lr = lane & 3;

    float acc[4][4][4];
#pragma unroll
    for (int mi = 0; mi < 4; mi++)
#pragma unroll
        for (int ni = 0; ni < 4; ni++)
#pragma unroll
            for (int r = 0; r < 4; r++) acc[mi][ni][r] = 0.f;

    // loaders: A tile 128x16 words = 512 uint4 (2/thread); B 16x128 = 512 uint4
    int aIdx0 = tid, aIdx1 = tid + 256;
    int ar0 = aIdx0 >> 2, ac0 = (aIdx0 & 3) << 2;
    int ar1 = aIdx1 >> 2, ac1 = (aIdx1 & 3) << 2;
    int br0 = aIdx0 >> 5, bc0 = (aIdx0 & 31) << 2;
    int br1 = aIdx1 >> 5, bc1 = (aIdx1 & 31) << 2;

    const uint32_t* Ab = Ah + (size_t)bm * KW;
    const uint32_t* Bb = Bh + bn;

    uint4 a0 = *(const uint4*)(Ab + (size_t)ar0 * KW + ac0);
    uint4 a1 = *(const uint4*)(Ab + (size_t)ar1 * KW + ac1);
    uint4 b0 = *(const uint4*)(Bb + (size_t)br0 * N + bc0);
    uint4 b1 = *(const uint4*)(Bb + (size_t)br1 * N + bc1);

    for (int t = 0; t < NT; t++) {
        __syncthreads();
        *(uint4*)&As[ar0 * 20 + ac0] = a0;
        *(uint4*)&As[ar1 * 20 + ac1] = a1;
        *(uint4*)&Bs[br0 * 136 + bc0] = b0;
        *(uint4*)&Bs[br1 * 136 + bc1] = b1;
        __syncthreads();

        if (t + 1 < NT) {               // prefetch next tile under the MMAs
            int kw = (t + 1) * 16;
            a0 = *(const uint4*)(Ab + (size_t)ar0 * KW + kw + ac0);
            a1 = *(const uint4*)(Ab + (size_t)ar1 * KW + kw + ac1);
            b0 = *(const uint4*)(Bb + (size_t)(kw + br0) * N + bc0);
            b1 = *(const uint4*)(Bb + (size_t)(kw + br1) * N + bc1);
        }

#pragma unroll
        for (int ks = 0; ks < 2; ks++) {
            int kp = ks * 8;
            uint32_t af[4][4], bf[4][2];
#pragma unroll
            for (int mi = 0; mi < 4; mi++) {
                int r0 = wm + mi * 16 + lq;
                af[mi][0] = As[r0 * 20 + kp + lr];
                af[mi][1] = As[(r0 + 8) * 20 + kp + lr];
                af[mi][2] = As[r0 * 20 + kp + 4 + lr];
                af[mi][3] = As[(r0 + 8) * 20 + kp + 4 + lr];
            }
#pragma unroll
            for (int ni = 0; ni < 4; ni++) {
                int c0 = wn + ni * 8 + lq;
                bf[ni][0] = Bs[(kp + lr) * 136 + c0];
                bf[ni][1] = Bs[(kp + 4 + lr) * 136 + c0];
            }
#pragma unroll
            for (int mi = 0; mi < 4; mi++)
#pragma unroll
                for (int ni = 0; ni < 4; ni++)
                    MMA_F16(acc[mi][ni], af[mi][0], af[mi][1], af[mi][2], af[mi][3],
                            bf[ni][0], bf[ni][1]);
        }
    }

#pragma unroll
    for (int mi = 0; mi < 4; mi++)
#pragma unroll
        for (int ni = 0; ni < 4; ni++) {
            int r = bm + wm + mi * 16 + lq;
            int c = bn + wn + ni * 8 + lr * 2;
            *(float2*)(C + (size_t)r * N + c) =
                make_float2(acc[mi][ni][0], acc[mi][ni][1]);
            *(float2*)(C + (size_t)(r + 8) * N + c) =
                make_float2(acc[mi][ni][2], acc[mi][ni][3]);
        }
}

// ---------------- Phase A: per-chunk KV = phi(K)^T V  and  kz = sum phi(k) ----
__global__ __launch_bounds__(256) void chunk_kv_kernel() {
    int bid = blockIdx.x;
    int bh = bid >> 5, c = bid & 31;
    int b = bh >> 4, h = bh & 15;
    int tid = threadIdx.x;
    __shared__ float sK[64][65];
    __shared__ float sV[64][65];

    const float* base = g_qkv + (size_t)(b * TB + c * 64) * (3 * CB) + h * 64;
#pragma unroll
    for (int it = 0; it < 4; it++) {
        int idx = tid + it * 256;
        int r = idx >> 4;
        int c4 = (idx & 15) << 2;
        float4 kk = *(const float4*)(base + (size_t)r * (3 * CB) + CB + c4);
        float4 vv = *(const float4*)(base + (size_t)r * (3 * CB) + 2 * CB + c4);
        sK[r][c4 + 0] = phi(kk.x); sK[r][c4 + 1] = phi(kk.y);
        sK[r][c4 + 2] = phi(kk.z); sK[r][c4 + 3] = phi(kk.w);
        sV[r][c4 + 0] = vv.x; sV[r][c4 + 1] = vv.y;
        sV[r][c4 + 2] = vv.z; sV[r][c4 + 3] = vv.w;
    }
    __syncthreads();

    int ii0 = (tid >> 4) << 2;
    int jj0 = (tid & 15) << 2;
    float a[4][4];
#pragma unroll
    for (int i = 0; i < 4; i++)
#pragma unroll
        for (int j = 0; j < 4; j++) a[i][j] = 0.f;

#pragma unroll 4
    for (int t = 0; t < 64; t++) {
        float kr[4], vr[4];
#pragma unroll
        for (int i = 0; i < 4; i++) kr[i] = sK[t][ii0 + i];
#pragma unroll
        for (int j = 0; j < 4; j++) vr[j] = sV[t][jj0 + j];
#pragma unroll
        for (int i = 0; i < 4; i++)
#pragma unroll
            for (int j = 0; j < 4; j++)
                a[i][j] += kr[i] * vr[j];
    }

    float* kvout = g_kv + (size_t)(bh * NCH + c) * (DD * DD);
#pragma unroll
    for (int i = 0; i < 4; i++)
        *(float4*)&kvout[(ii0 + i) * 64 + jj0] =
            make_float4(a[i][0], a[i][1], a[i][2], a[i][3]);

    if (tid < 64) {
        float s = 0.f;
#pragma unroll 8
        for (int t = 0; t < 64; t++) s += sK[t][tid];
        g_kz[(size_t)(bh * NCH + c) * 64 + tid] = s;
    }
}

// ---------------- Phase B: exclusive prefix over chunks ------------------------
__global__ void scan_all_kernel() {
    int e = blockIdx.x * 256 + threadIdx.x;
    if (e < BHN * 4096) {
        int bh = e >> 12, ij = e & 4095;
        float* p = g_kv + (size_t)bh * NCH * 4096 + ij;
        float run = 0.f;
#pragma unroll 4
        for (int c = 0; c < NCH; c++) {
            float v = p[(size_t)c * 4096];
            p[(size_t)c * 4096] = run;
            run += v;
        }
    } else if (e < BHN * 4096 + BHN * 64) {
        int e2 = e - BHN * 4096;
        int bh = e2 >> 6, i = e2 & 63;
        float* p = g_kz + (size_t)bh * NCH * 64 + i;
        float run = 0.f;
#pragma unroll 4
        for (int c = 0; c < NCH; c++) {
            float v = p[(size_t)c * 64];
            p[(size_t)c * 64] = run;
            run += v;
        }
    }
}

// ---------------- Phase C: tensor-core per-chunk output ------------------------
// Epilogue writes fp16x2-packed y straight into g_yh (proj GEMM A operand).
#define ATTN_SMEM_WORDS (64*68 + 64*72*3 + 64)
#define ATTN_SMEM_BYTES (ATTN_SMEM_WORDS * 4)

__global__ __launch_bounds__(128) void attn_out_tc_kernel() {
    extern __shared__ uint32_t sm[];
    uint32_t* sQ  = sm;                          // [64][68]
    uint32_t* sKt = sm + 64 * 68;                // [64][72] (phase 1 only)
    uint32_t* sP  = sKt;                         // alias (phase 2)
    uint32_t* sS  = sm + 64 * 68 + 64 * 72;      // [64][72]
    uint32_t* sV  = sS + 64 * 72;                // [64][72]
    float* sDen = (float*)(sV + 64 * 72);        // [64]

    int bid = blockIdx.x;
    int bh = bid >> 5, cidx = bid & 31;
    int b = bh >> 4, h = bh & 15;
    int tid = threadIdx.x;
    int lane = tid & 31;
    int warp = tid >> 5;
    int wrow = warp * 16;
    int lq = lane >> 2, lr = lane & 3;

    const float* base = g_qkv + (size_t)(b * TB + cidx * 64) * (3 * CB) + h * 64;
    const float* Sg = g_kv + (size_t)(bh * NCH + cidx) * 4096;

#pragma unroll
    for (int it = 0; it < 8; it++) {
        int idx = it * 128 + tid;
        int r = idx >> 4, c4 = (idx & 15) << 2;
        float4 q4 = *(const float4*)(base + (size_t)r * (3 * CB) + c4);
        float4 v4 = *(const float4*)(base + (size_t)r * (3 * CB) + 2 * CB + c4);
        float4 s4 = *(const float4*)(Sg + r * 64 + c4);
        sQ[r * 68 + c4 + 0] = f2tf32(phi(q4.x));
        sQ[r * 68 + c4 + 1] = f2tf32(phi(q4.y));
        sQ[r * 68 + c4 + 2] = f2tf32(phi(q4.z));
        sQ[r * 68 + c4 + 3] = f2tf32(phi(q4.w));
        sV[r * 72 + c4 + 0] = f2tf32(v4.x);
        sV[r * 72 + c4 + 1] = f2tf32(v4.y);
        sV[r * 72 + c4 + 2] = f2tf32(v4.z);
        sV[r * 72 + c4 + 3] = f2tf32(v4.w);
        sS[r * 72 + c4 + 0] = f2tf32(s4.x);
        sS[r * 72 + c4 + 1] = f2tf32(s4.y);
        sS[r * 72 + c4 + 2] = f2tf32(s4.z);
        sS[r * 72 + c4 + 3] = f2tf32(s4.w);
        int tt = idx & 63, kc = (idx >> 6) << 2;
        float4 k4 = *(const float4*)(base + (size_t)tt * (3 * CB) + CB + kc);
        sKt[(kc + 0) * 72 + tt] = f2tf32(phi(k4.x));
        sKt[(kc + 1) * 72 + tt] = f2tf32(phi(k4.y));
        sKt[(kc + 2) * 72 + tt] = f2tf32(phi(k4.z));
        sKt[(kc + 3) * 72 + tt] = f2tf32(phi(k4.w));
    }
    if (tid < 64) {
        sV[tid * 72 + 64] = 0x3f800000u;
        sS[tid * 72 + 64] = f2tf32(g_kz[(size_t)(bh * NCH + cidx) * 64 + tid]);
#pragma unroll
        for (int j = 65; j < 72; j++) { sV[tid * 72 + j] = 0u; sS[tid * 72 + j] = 0u; }
    }
    __syncthreads();

    int r0 = wrow + lq, r1 = r0 + 8;

    float pc[8][4];
#pragma unroll
    for (int nt = 0; nt < 8; nt++)
#pragma unroll
        for (int r = 0; r < 4; r++) pc[nt][r] = 0.f;

#pragma unroll
    for (int ks = 0; ks < 8; ks++) {
        int kb = ks * 8;
        uint32_t a0 = sQ[r0 * 68 + kb + lr];
        uint32_t a1 = sQ[r1 * 68 + kb + lr];
        uint32_t a2 = sQ[r0 * 68 + kb + 4 + lr];
        uint32_t a3 = sQ[r1 * 68 + kb + 4 + lr];
#pragma unroll
        for (int nt = 0; nt < 8; nt++) {
            uint32_t b0 = sKt[(kb + lr) * 72 + nt * 8 + lq];
            uint32_t b1 = sKt[(kb + 4 + lr) * 72 + nt * 8 + lq];
            MMA_TF32(pc[nt], a0, a1, a2, a3, b0, b1);
        }
    }
    __syncthreads();

#pragma unroll
    for (int nt = 0; nt < 8; nt++) {
        int s0 = nt * 8 + 2 * lr;
        sP[r0 * 68 + s0    ] = f2tf32((s0     <= r0) ? pc[nt][0] : 0.f);
        sP[r0 * 68 + s0 + 1] = f2tf32((s0 + 1 <= r0) ? pc[nt][1] : 0.f);
        sP[r1 * 68 + s0    ] = f2tf32((s0     <= r1) ? pc[nt][2] : 0.f);
        sP[r1 * 68 + s0 + 1] = f2tf32((s0 + 1 <= r1) ? pc[nt][3] : 0.f);
    }
    __syncwarp();

    float acc[9][4];
#pragma unroll
    for (int nt = 0; nt < 9; nt++)
#pragma unroll
        for (int r = 0; r < 4; r++) acc[nt][r] = 0.f;

#pragma unroll
    for (int ks = 0; ks < 8; ks++) {
        int kb = ks * 8;
        uint32_t q0 = sQ[r0 * 68 + kb + lr];
        uint32_t q1 = sQ[r1 * 68 + kb + lr];
        uint32_t q2 = sQ[r0 * 68 + kb + 4 + lr];
        uint32_t q3 = sQ[r1 * 68 + kb + 4 + lr];
        uint32_t p0 = sP[r0 * 68 + kb + lr];
        uint32_t p1 = sP[r1 * 68 + kb + lr];
        uint32_t p2 = sP[r0 * 68 + kb + 4 + lr];
        uint32_t p3 = sP[r1 * 68 + kb + 4 + lr];
#pragma unroll
        for (int nt = 0; nt < 9; nt++) {
            int n0 = nt * 8;
            uint32_t bs0 = sS[(kb + lr) * 72 + n0 + lq];
            uint32_t bs1 = sS[(kb + 4 + lr) * 72 + n0 + lq];
            MMA_TF32(acc[nt], q0, q1, q2, q3, bs0, bs1);
            uint32_t bv0 = sV[(kb + lr) * 72 + n0 + lq];
            uint32_t bv1 = sV[(kb + 4 + lr) * 72 + n0 + lq];
            MMA_TF32(acc[nt], p0, p1, p2, p3, bv0, bv1);
        }
    }

    if (lr == 0) { sDen[r0] = acc[8][0]; sDen[r1] = acc[8][2]; }
    __syncwarp();
    float inv0 = 1.f / (sDen[r0] + 1e-6f);
    float inv1 = 1.f / (sDen[r1] + 1e-6f);

    uint32_t* yb = g_yh + (size_t)(b * TB + cidx * 64) * (CB / 2) + h * 32;
#pragma unroll
    for (int nt = 0; nt < 8; nt++) {
        int w = nt * 4 + lr;    // word index (covers cols 2w, 2w+1)
        yb[(size_t)r0 * (CB / 2) + w] = pack_h2(acc[nt][0] * inv0, acc[nt][1] * inv0);
        yb[(size_t)r1 * (CB / 2) + w] = pack_h2(acc[nt][2] * inv1, acc[nt][3] * inv1);
    }
}

// ---------------- launch ------------------------------------------------------
extern "C" void kernel_launch(void* const* d_in, const int* in_sizes, int n_in,
                              void* d_out, int out_size) {
    const float* x      = (const float*)d_in[0];
    const float* w_attn = (const float*)d_in[1];
    const float* w_proj = (const float*)d_in[2];
    float* out = (float*)d_out;

    cudaFuncSetAttribute(attn_out_tc_kernel,
                         cudaFuncAttributeMaxDynamicSharedMemorySize, ATTN_SMEM_BYTES);

    float *qkv;
    uint32_t *xh, *yh, *wah, *wph;
    cudaGetSymbolAddress((void**)&qkv, g_qkv);
    cudaGetSymbolAddress((void**)&xh,  g_xh);
    cudaGetSymbolAddress((void**)&yh,  g_yh);
    cudaGetSymbolAddress((void**)&wah, g_wah);
    cudaGetSymbolAddress((void**)&wph, g_wph);

    int nxa = BSZ * TB * CB / 2;                  // x pair-words
    int nwa = (CB / 2) * 3 * CB;                  // w_attn words
    int nwp = (CB / 2) * CB;                      // w_proj words
    packA_kernel<<<(nxa + 255) / 256, 256>>>((const float2*)x, xh, nxa);
    packB_kernel<<<(nwa + 255) / 256, 256>>>(w_attn, wah, 3 * CB, nwa);
    packB_kernel<<<(nwp + 255) / 256, 256>>>(w_proj, wph, CB, nwp);

    dim3 g1(3 * CB / 128, BSZ * TB / 128);   // (24, 32)
    hgemm_kernel<<<g1, 256>>>(xh, wah, qkv, 3 * CB);

    chunk_kv_kernel<<<BHN * NCH, 256>>>();
    scan_all_kernel<<<(BHN * 4096 + BHN * 64 + 255) / 256, 256>>>();
    attn_out_tc_kernel<<<BHN * NCH, 128, ATTN_SMEM_BYTES>>>();

    dim3 g2(CB / 128, BSZ * TB / 128);       // (8, 32)
    hgemm_kernel<<<g2, 256>>>(yh, wph, out, CB);
}

// round 14
// speedup vs baseline: 1.5111x; 1.0240x over previous
#include <cuda_runtime.h>
#include <math.h>
#include <stdint.h>

#define TB 2048
#define CB 1024
#define BSZ 2
#define HH 16
#define DD 64
#define NCH 32   // chunks of 64 along T
#define BHN 32   // BSZ*HH

// ---------------- scratch (static device allocations; no cudaMalloc) ----------
__device__ float    g_qkv[(size_t)BSZ * TB * 3 * CB];      // 50.3 MB fp32
__device__ float    g_kv [(size_t)BHN * NCH * DD * DD];
__device__ float    g_kz [(size_t)BHN * NCH * DD];
__device__ uint32_t g_xh [(size_t)BSZ * TB * CB / 2];      // x packed fp16x2 along K
__device__ uint32_t g_yh [(size_t)BSZ * TB * CB / 2];      // y packed fp16x2 along K
__device__ uint32_t g_wah[(size_t)CB / 2 * 3 * CB];        // w_attn [K/2][3072] k-pair words
__device__ uint32_t g_wph[(size_t)CB / 2 * CB];            // w_proj [K/2][1024]

__device__ __forceinline__ float phi(float x) { return x > 0.f ? x + 1.f : expf(x); }

__device__ __forceinline__ uint32_t f2tf32(float x) {
    uint32_t r;
    asm("cvt.rna.tf32.f32 %0, %1;" : "=r"(r) : "f"(x));
    return r;
}
__device__ __forceinline__ uint32_t pack_h2(float lo, float hi) {
    uint32_t r;                              // low 16 bits = lo (lower k index)
    asm("cvt.rn.f16x2.f32 %0, %1, %2;" : "=r"(r) : "f"(hi), "f"(lo));
    return r;
}

#define MMA_TF32(C, A0, A1, A2, A3, B0, B1)                                     \
    asm volatile(                                                               \
        "mma.sync.aligned.m16n8k8.row.col.f32.tf32.tf32.f32 "                   \
        "{%0,%1,%2,%3}, {%4,%5,%6,%7}, {%8,%9}, {%0,%1,%2,%3};"                 \
        : "+f"((C)[0]), "+f"((C)[1]), "+f"((C)[2]), "+f"((C)[3])                \
        : "r"(A0), "r"(A1), "r"(A2), "r"(A3), "r"(B0), "r"(B1))

#define MMA_F16(C, A0, A1, A2, A3, B0, B1)                                      \
    asm volatile(                                                               \
        "mma.sync.aligned.m16n8k16.row.col.f32.f16.f16.f32 "                    \
        "{%0,%1,%2,%3}, {%4,%5,%6,%7}, {%8,%9}, {%0,%1,%2,%3};"                 \
        : "+f"((C)[0]), "+f"((C)[1]), "+f"((C)[2]), "+f"((C)[3])                \
        : "r"(A0), "r"(A1), "r"(A2), "r"(A3), "r"(B0), "r"(B1))

// ---------------- pack pre-passes ---------------------------------------------
__global__ __launch_bounds__(256) void packA_kernel(const float2* __restrict__ src,
                                                    uint32_t* __restrict__ dst, int n) {
    int i = blockIdx.x * 256 + threadIdx.x;
    if (i < n) {
        float2 v = src[i];
        dst[i] = pack_h2(v.x, v.y);
    }
}
// B [K][N] fp32 -> [K/2][N] words, word(kp,n) = (f16 B[2kp][n], f16 B[2kp+1][n])
__global__ __launch_bounds__(256) void packB_kernel(const float* __restrict__ src,
                                                    uint32_t* __restrict__ dst,
                                                    int N, int total) {
    int i = blockIdx.x * 256 + threadIdx.x;
    if (i < total) {
        int kp = i / N, n = i - kp * N;
        float lo = src[(size_t)(2 * kp) * N + n];
        float hi = src[(size_t)(2 * kp + 1) * N + n];
        dst[i] = pack_h2(lo, hi);
    }
}

// ---------------- FP16 tensor GEMM: C(MxN)=A(Mx1024)@B(1024xN), fp32 accum ----
// 128x128 block, 4 warps (2x2), warp tile 64x64, k-tile 32 (16 word-pairs).
// A redundancy 2x (was 4x): 33% less fragment LDS traffic per FLOP.
__global__ __launch_bounds__(128) void hgemm_kernel(const uint32_t* __restrict__ Ah,
                                                    const uint32_t* __restrict__ Bh,
                                                    float* __restrict__ C, int N) {
    __shared__ uint32_t As[128 * 20];
    __shared__ uint32_t Bs[16 * 136];
    const int KW = 512;                 // words per A row
    const int NT = 32;                  // k tiles

    int tid  = threadIdx.x;
    int lane = tid & 31;
    int warp = tid >> 5;
    int wm = (warp >> 1) * 64;
    int wn = (warp & 1) * 64;
    int bm = blockIdx.y * 128;
    int bn = blockIdx.x * 128;
    const int lq = lane >> 2;
    const int lr = lane & 3;

    float acc[4][8][4];
#pragma unroll
    for (int mi = 0; mi < 4; mi++)
#pragma unroll
        for (int ni = 0; ni < 8; ni++)
#pragma unroll
            for (int r = 0; r < 4; r++) acc[mi][ni][r] = 0.f;

    // loaders (128 threads): A tile 128x16 words = 512 uint4 (4/thread);
    // B tile 16x128 words = 512 uint4 (4/thread)
    int ar[4], ac[4], br[4], bc[4];
#pragma unroll
    for (int i = 0; i < 4; i++) {
        int idx = tid + i * 128;
        ar[i] = idx >> 2;  ac[i] = (idx & 3) << 2;
        br[i] = idx >> 5;  bc[i] = (idx & 31) << 2;
    }

    const uint32_t* Ab = Ah + (size_t)bm * KW;
    const uint32_t* Bb = Bh + bn;

    uint4 a[4], b[4];
#pragma unroll
    for (int i = 0; i < 4; i++) {
        a[i] = *(const uint4*)(Ab + (size_t)ar[i] * KW + ac[i]);
        b[i] = *(const uint4*)(Bb + (size_t)br[i] * N + bc[i]);
    }

    for (int t = 0; t < NT; t++) {
        __syncthreads();
#pragma unroll
        for (int i = 0; i < 4; i++) {
            *(uint4*)&As[ar[i] * 20 + ac[i]] = a[i];
            *(uint4*)&Bs[br[i] * 136 + bc[i]] = b[i];
        }
        __syncthreads();

        if (t + 1 < NT) {               // prefetch next tile under the MMAs
            int kw = (t + 1) * 16;
#pragma unroll
            for (int i = 0; i < 4; i++) {
                a[i] = *(const uint4*)(Ab + (size_t)ar[i] * KW + kw + ac[i]);
                b[i] = *(const uint4*)(Bb + (size_t)(kw + br[i]) * N + bc[i]);
            }
        }

#pragma unroll
        for (int ks = 0; ks < 2; ks++) {
            int kp = ks * 8;
            uint32_t af[4][4], bf[8][2];
#pragma unroll
            for (int mi = 0; mi < 4; mi++) {
                int r0 = wm + mi * 16 + lq;
                af[mi][0] = As[r0 * 20 + kp + lr];
                af[mi][1] = As[(r0 + 8) * 20 + kp + lr];
                af[mi][2] = As[r0 * 20 + kp + 4 + lr];
                af[mi][3] = As[(r0 + 8) * 20 + kp + 4 + lr];
            }
#pragma unroll
            for (int ni = 0; ni < 8; ni++) {
                int c0 = wn + ni * 8 + lq;
                bf[ni][0] = Bs[(kp + lr) * 136 + c0];
                bf[ni][1] = Bs[(kp + 4 + lr) * 136 + c0];
            }
#pragma unroll
            for (int mi = 0; mi < 4; mi++)
#pragma unroll
                for (int ni = 0; ni < 8; ni++)
                    MMA_F16(acc[mi][ni], af[mi][0], af[mi][1], af[mi][2], af[mi][3],
                            bf[ni][0], bf[ni][1]);
        }
    }

#pragma unroll
    for (int mi = 0; mi < 4; mi++)
#pragma unroll
        for (int ni = 0; ni < 8; ni++) {
            int r = bm + wm + mi * 16 + lq;
            int c = bn + wn + ni * 8 + lr * 2;
            *(float2*)(C + (size_t)r * N + c) =
                make_float2(acc[mi][ni][0], acc[mi][ni][1]);
            *(float2*)(C + (size_t)(r + 8) * N + c) =
                make_float2(acc[mi][ni][2], acc[mi][ni][3]);
        }
}

// ---------------- Phase A: per-chunk KV = phi(K)^T V  and  kz = sum phi(k) ----
__global__ __launch_bounds__(256) void chunk_kv_kernel() {
    int bid = blockIdx.x;
    int bh = bid >> 5, c = bid & 31;
    int b = bh >> 4, h = bh & 15;
    int tid = threadIdx.x;
    __shared__ float sK[64][65];
    __shared__ float sV[64][65];

    const float* base = g_qkv + (size_t)(b * TB + c * 64) * (3 * CB) + h * 64;
#pragma unroll
    for (int it = 0; it < 4; it++) {
        int idx = tid + it * 256;
        int r = idx >> 4;
        int c4 = (idx & 15) << 2;
        float4 kk = *(const float4*)(base + (size_t)r * (3 * CB) + CB + c4);
        float4 vv = *(const float4*)(base + (size_t)r * (3 * CB) + 2 * CB + c4);
        sK[r][c4 + 0] = phi(kk.x); sK[r][c4 + 1] = phi(kk.y);
        sK[r][c4 + 2] = phi(kk.z); sK[r][c4 + 3] = phi(kk.w);
        sV[r][c4 + 0] = vv.x; sV[r][c4 + 1] = vv.y;
        sV[r][c4 + 2] = vv.z; sV[r][c4 + 3] = vv.w;
    }
    __syncthreads();

    int ii0 = (tid >> 4) << 2;
    int jj0 = (tid & 15) << 2;
    float a[4][4];
#pragma unroll
    for (int i = 0; i < 4; i++)
#pragma unroll
        for (int j = 0; j < 4; j++) a[i][j] = 0.f;

#pragma unroll 4
    for (int t = 0; t < 64; t++) {
        float kr[4], vr[4];
#pragma unroll
        for (int i = 0; i < 4; i++) kr[i] = sK[t][ii0 + i];
#pragma unroll
        for (int j = 0; j < 4; j++) vr[j] = sV[t][jj0 + j];
#pragma unroll
        for (int i = 0; i < 4; i++)
#pragma unroll
            for (int j = 0; j < 4; j++)
                a[i][j] += kr[i] * vr[j];
    }

    float* kvout = g_kv + (size_t)(bh * NCH + c) * (DD * DD);
#pragma unroll
    for (int i = 0; i < 4; i++)
        *(float4*)&kvout[(ii0 + i) * 64 + jj0] =
            make_float4(a[i][0], a[i][1], a[i][2], a[i][3]);

    if (tid < 64) {
        float s = 0.f;
#pragma unroll 8
        for (int t = 0; t < 64; t++) s += sK[t][tid];
        g_kz[(size_t)(bh * NCH + c) * 64 + tid] = s;
    }
}

// ---------------- Phase B: exclusive prefix over chunks ------------------------
__global__ void scan_all_kernel() {
    int e = blockIdx.x * 256 + threadIdx.x;
    if (e < BHN * 4096) {
        int bh = e >> 12, ij = e & 4095;
        float* p = g_kv + (size_t)bh * NCH * 4096 + ij;
        float run = 0.f;
#pragma unroll 4
        for (int c = 0; c < NCH; c++) {
            float v = p[(size_t)c * 4096];
            p[(size_t)c * 4096] = run;
            run += v;
        }
    } else if (e < BHN * 4096 + BHN * 64) {
        int e2 = e - BHN * 4096;
        int bh = e2 >> 6, i = e2 & 63;
        float* p = g_kz + (size_t)bh * NCH * 64 + i;
        float run = 0.f;
#pragma unroll 4
        for (int c = 0; c < NCH; c++) {
            float v = p[(size_t)c * 64];
            p[(size_t)c * 64] = run;
            run += v;
        }
    }
}

// ---------------- Phase C: tensor-core per-chunk output ------------------------
// Epilogue writes fp16x2-packed y straight into g_yh (proj GEMM A operand).
#define ATTN_SMEM_WORDS (64*68 + 64*72*3 + 64)
#define ATTN_SMEM_BYTES (ATTN_SMEM_WORDS * 4)

__global__ __launch_bounds__(128) void attn_out_tc_kernel() {
    extern __shared__ uint32_t sm[];
    uint32_t* sQ  = sm;                          // [64][68]
    uint32_t* sKt = sm + 64 * 68;                // [64][72] (phase 1 only)
    uint32_t* sP  = sKt;                         // alias (phase 2)
    uint32_t* sS  = sm + 64 * 68 + 64 * 72;      // [64][72]
    uint32_t* sV  = sS + 64 * 72;                // [64][72]
    float* sDen = (float*)(sV + 64 * 72);        // [64]

    int bid = blockIdx.x;
    int bh = bid >> 5, cidx = bid & 31;
    int b = bh >> 4, h = bh & 15;
    int tid = threadIdx.x;
    int lane = tid & 31;
    int warp = tid >> 5;
    int wrow = warp * 16;
    int lq = lane >> 2, lr = lane & 3;

    const float* base = g_qkv + (size_t)(b * TB + cidx * 64) * (3 * CB) + h * 64;
    const float* Sg = g_kv + (size_t)(bh * NCH + cidx) * 4096;

#pragma unroll
    for (int it = 0; it < 8; it++) {
        int idx = it * 128 + tid;
        int r = idx >> 4, c4 = (idx & 15) << 2;
        float4 q4 = *(const float4*)(base + (size_t)r * (3 * CB) + c4);
        float4 v4 = *(const float4*)(base + (size_t)r * (3 * CB) + 2 * CB + c4);
        float4 s4 = *(const float4*)(Sg + r * 64 + c4);
        sQ[r * 68 + c4 + 0] = f2tf32(phi(q4.x));
        sQ[r * 68 + c4 + 1] = f2tf32(phi(q4.y));
        sQ[r * 68 + c4 + 2] = f2tf32(phi(q4.z));
        sQ[r * 68 + c4 + 3] = f2tf32(phi(q4.w));
        sV[r * 72 + c4 + 0] = f2tf32(v4.x);
        sV[r * 72 + c4 + 1] = f2tf32(v4.y);
        sV[r * 72 + c4 + 2] = f2tf32(v4.z);
        sV[r * 72 + c4 + 3] = f2tf32(v4.w);
        sS[r * 72 + c4 + 0] = f2tf32(s4.x);
        sS[r * 72 + c4 + 1] = f2tf32(s4.y);
        sS[r * 72 + c4 + 2] = f2tf32(s4.z);
        sS[r * 72 + c4 + 3] = f2tf32(s4.w);
        int tt = idx & 63, kc = (idx >> 6) << 2;
        float4 k4 = *(const float4*)(base + (size_t)tt * (3 * CB) + CB + kc);
        sKt[(kc + 0) * 72 + tt] = f2tf32(phi(k4.x));
        sKt[(kc + 1) * 72 + tt] = f2tf32(phi(k4.y));
        sKt[(kc + 2) * 72 + tt] = f2tf32(phi(k4.z));
        sKt[(kc + 3) * 72 + tt] = f2tf32(phi(k4.w));
    }
    if (tid < 64) {
        sV[tid * 72 + 64] = 0x3f800000u;
        sS[tid * 72 + 64] = f2tf32(g_kz[(size_t)(bh * NCH + cidx) * 64 + tid]);
#pragma unroll
        for (int j = 65; j < 72; j++) { sV[tid * 72 + j] = 0u; sS[tid * 72 + j] = 0u; }
    }
    __syncthreads();

    int r0 = wrow + lq, r1 = r0 + 8;

    float pc[8][4];
#pragma unroll
    for (int nt = 0; nt < 8; nt++)
#pragma unroll
        for (int r = 0; r < 4; r++) pc[nt][r] = 0.f;

#pragma unroll
    for (int ks = 0; ks < 8; ks++) {
        int kb = ks * 8;
        uint32_t a0 = sQ[r0 * 68 + kb + lr];
        uint32_t a1 = sQ[r1 * 68 + kb + lr];
        uint32_t a2 = sQ[r0 * 68 + kb + 4 + lr];
        uint32_t a3 = sQ[r1 * 68 + kb + 4 + lr];
#pragma unroll
        for (int nt = 0; nt < 8; nt++) {
            uint32_t b0 = sKt[(kb + lr) * 72 + nt * 8 + lq];
            uint32_t b1 = sKt[(kb + 4 + lr) * 72 + nt * 8 + lq];
            MMA_TF32(pc[nt], a0, a1, a2, a3, b0, b1);
        }
    }
    __syncthreads();

#pragma unroll
    for (int nt = 0; nt < 8; nt++) {
        int s0 = nt * 8 + 2 * lr;
        sP[r0 * 68 + s0    ] = f2tf32((s0     <= r0) ? pc[nt][0] : 0.f);
        sP[r0 * 68 + s0 + 1] = f2tf32((s0 + 1 <= r0) ? pc[nt][1] : 0.f);
        sP[r1 * 68 + s0    ] = f2tf32((s0     <= r1) ? pc[nt][2] : 0.f);
        sP[r1 * 68 + s0 + 1] = f2tf32((s0 + 1 <= r1) ? pc[nt][3] : 0.f);
    }
    __syncwarp();

    float acc[9][4];
#pragma unroll
    for (int nt = 0; nt < 9; nt++)
#pragma unroll
        for (int r = 0; r < 4; r++) acc[nt][r] = 0.f;

#pragma unroll
    for (int ks = 0; ks < 8; ks++) {
        int kb = ks * 8;
        uint32_t q0 = sQ[r0 * 68 + kb + lr];
        uint32_t q1 = sQ[r1 * 68 + kb + lr];
        uint32_t q2 = sQ[r0 * 68 + kb + 4 + lr];
        uint32_t q3 = sQ[r1 * 68 + kb + 4 + lr];
        uint32_t p0 = sP[r0 * 68 + kb + lr];
        uint32_t p1 = sP[r1 * 68 + kb + lr];
        uint32_t p2 = sP[r0 * 68 + kb + 4 + lr];
        uint32_t p3 = sP[r1 * 68 + kb + 4 + lr];
#pragma unroll
        for (int nt = 0; nt < 9; nt++) {
            int n0 = nt * 8;
            uint32_t bs0 = sS[(kb + lr) * 72 + n0 + lq];
            uint32_t bs1 = sS[(kb + 4 + lr) * 72 + n0 + lq];
            MMA_TF32(acc[nt], q0, q1, q2, q3, bs0, bs1);
            uint32_t bv0 = sV[(kb + lr) * 72 + n0 + lq];
            uint32_t bv1 = sV[(kb + 4 + lr) * 72 + n0 + lq];
            MMA_TF32(acc[nt], p0, p1, p2, p3, bv0, bv1);
        }
    }

    if (lr == 0) { sDen[r0] = acc[8][0]; sDen[r1] = acc[8][2]; }
    __syncwarp();
    float inv0 = 1.f / (sDen[r0] + 1e-6f);
    float inv1 = 1.f / (sDen[r1] + 1e-6f);

    uint32_t* yb = g_yh + (size_t)(b * TB + cidx * 64) * (CB / 2) + h * 32;
#pragma unroll
    for (int nt = 0; nt < 8; nt++) {
        int w = nt * 4 + lr;    // word index (covers cols 2w, 2w+1)
        yb[(size_t)r0 * (CB / 2) + w] = pack_h2(acc[nt][0] * inv0, acc[nt][1] * inv0);
        yb[(size_t)r1 * (CB / 2) + w] = pack_h2(acc[nt][2] * inv1, acc[nt][3] * inv1);
    }
}

// ---------------- launch ------------------------------------------------------
extern "C" void kernel_launch(void* const* d_in, const int* in_sizes, int n_in,
                              void* d_out, int out_size) {
    const float* x      = (const float*)d_in[0];
    const float* w_attn = (const float*)d_in[1];
    const float* w_proj = (const float*)d_in[2];
    float* out = (float*)d_out;

    cudaFuncSetAttribute(attn_out_tc_kernel,
                         cudaFuncAttributeMaxDynamicSharedMemorySize, ATTN_SMEM_BYTES);

    float *qkv;
    uint32_t *xh, *yh, *wah, *wph;
    cudaGetSymbolAddress((void**)&qkv, g_qkv);
    cudaGetSymbolAddress((void**)&xh,  g_xh);
    cudaGetSymbolAddress((void**)&yh,  g_yh);
    cudaGetSymbolAddress((void**)&wah, g_wah);
    cudaGetSymbolAddress((void**)&wph, g_wph);

    int nxa = BSZ * TB * CB / 2;                  // x pair-words
    int nwa = (CB / 2) * 3 * CB;                  // w_attn words
    int nwp = (CB / 2) * CB;                      // w_proj words
    packA_kernel<<<(nxa + 255) / 256, 256>>>((const float2*)x, xh, nxa);
    packB_kernel<<<(nwa + 255) / 256, 256>>>(w_attn, wah, 3 * CB, nwa);
    packB_kernel<<<(nwp + 255) / 256, 256>>>(w_proj, wph, CB, nwp);

    dim3 g1(3 * CB / 128, BSZ * TB / 128);   // (24, 32)
    hgemm_kernel<<<g1, 128>>>(xh, wah, qkv, 3 * CB);

    chunk_kv_kernel<<<BHN * NCH, 256>>>();
    scan_all_kernel<<<(BHN * 4096 + BHN * 64 + 255) / 256, 256>>>();
    attn_out_tc_kernel<<<BHN * NCH, 128, ATTN_SMEM_BYTES>>>();

    dim3 g2(CB / 128, BSZ * TB / 128);       // (8, 32)
    hgemm_kernel<<<g2, 128>>>(yh, wph, out, CB);
}